// round 11
// baseline (speedup 1.0000x reference)
#include <cuda_runtime.h>
#include <math.h>

#define Bc     4
#define Sc     16
#define Dc     1024
#define DNc    2048
#define Kc     8
#define NBc    4
#define VOCABc 151936
#define NBLK   512
#define NTHR   128

// ---------------- device state (static; no allocation) ----------------
__device__ float g_Vst[2 * NBc * Bc * DNc];   // ping-pong V state [par][blk][b][n]
__device__ float g_u[NBc * Bc * Dc];          // PLIF output-neuron state
__device__ float g_xbuf[2][Bc * Dc];          // ping-pong spike vectors between blocks
__device__ float g_sp[Bc * DNc];              // internal spikes of current block
__device__ float g_frames[Kc * Bc * Dc];      // binary frames for current token
__device__ float g_decoded[Bc * Dc];          // weighted sum of output frames
__device__ float g_hh[Bc * Dc];               // decoded @ dec_W.T (+rmsnorm in place)

// software grid barrier state (self-resetting: count returns to 0, gen monotonic)
__device__ unsigned g_bar_count;
__device__ volatile unsigned g_bar_gen;

// ---------------- helpers ----------------
__device__ __forceinline__ float sigmf_(float a) { return 1.0f / (1.0f + expf(-a)); }
__device__ __forceinline__ float softplusf_(float a) {
    return fmaxf(a, 0.0f) + log1pf(expf(-fabsf(a)));
}
__device__ __forceinline__ float warp_sum(float v) {
    v += __shfl_xor_sync(0xffffffffu, v, 16);
    v += __shfl_xor_sync(0xffffffffu, v, 8);
    v += __shfl_xor_sync(0xffffffffu, v, 4);
    v += __shfl_xor_sync(0xffffffffu, v, 2);
    v += __shfl_xor_sync(0xffffffffu, v, 1);
    return v;
}
__device__ __forceinline__ float dot4(float acc, float4 wv, float4 av) {
    return fmaf(wv.x, av.x, fmaf(wv.y, av.y, fmaf(wv.z, av.z, fmaf(wv.w, av.w, acc))));
}

// Two-variable grid barrier. All 512 blocks are co-resident (launch_bounds(128,4)
// -> >=4 blocks/SM -> capacity 592 >= 512), so spinning is safe.
__device__ __forceinline__ void grid_sync() {
    __syncthreads();
    if (threadIdx.x == 0) {
        __threadfence();                       // release prior writes
        unsigned gen = g_bar_gen;
        if (atomicAdd(&g_bar_count, 1u) == (unsigned)(gridDim.x - 1)) {
            g_bar_count = 0;
            __threadfence();
            g_bar_gen = gen + 1;               // release
        } else {
            while (g_bar_gen == gen) __nanosleep(64);
        }
        __threadfence();                       // acquire
    }
    __syncthreads();
}

// NR output rows x 4 batch operands, 4-way column split across the block's 4 warps.
// Weight loads streamed (__ldcs); operands via __ldg (stay L1/L2-hot).
// Per-accumulator FMA order is IDENTICAL to the validated multi-kernel version.
// NF4 = float4 iterations per warp = L / 512 (L=1024 -> 2, L=2048 -> 4).
template <int NR, int NF4>
__device__ __forceinline__ void passN(
    const float* __restrict__ wrow0, int ldw,
    const float* __restrict__ px0, const float* __restrict__ px1,
    const float* __restrict__ px2, const float* __restrict__ px3,
    int warp, int lane, float* acc)
{
    const float4* a0 = (const float4*)px0;
    const float4* a1 = (const float4*)px1;
    const float4* a2 = (const float4*)px2;
    const float4* a3 = (const float4*)px3;
    int cbase = warp * NF4 * 32 + lane;
#pragma unroll
    for (int it = 0; it < NF4; ++it) {
        int idx = cbase + it * 32;
        float4 b0 = __ldg(a0 + idx);
        float4 b1 = __ldg(a1 + idx);
        float4 b2 = __ldg(a2 + idx);
        float4 b3 = __ldg(a3 + idx);
#pragma unroll
        for (int r = 0; r < NR; ++r) {
            const float4* wr = (const float4*)(wrow0 + (size_t)r * ldw);
            float4 q = __ldcs(wr + idx);
            acc[r * 4 + 0] = dot4(acc[r * 4 + 0], q, b0);
            acc[r * 4 + 1] = dot4(acc[r * 4 + 1], q, b1);
            acc[r * 4 + 2] = dot4(acc[r * 4 + 2], q, b2);
            acc[r * 4 + 3] = dot4(acc[r * 4 + 3], q, b3);
        }
    }
}

template <int NA>
__device__ __forceinline__ void reduceN(const float* acc, float (*sh)[4], int warp, int lane) {
#pragma unroll
    for (int i = 0; i < NA; ++i) {
        float v = warp_sum(acc[i]);
        if (lane == 0) sh[i][warp] = v;
    }
}

__device__ __forceinline__ const float* xsel_ptr(int sel) {
    return (sel < Kc) ? (g_frames + (size_t)sel * Bc * Dc) : g_xbuf[sel - Kc];
}

// ---------------- the whole model as ONE persistent kernel ----------------
__global__ void __launch_bounds__(NTHR, 4) snn_mono_kernel(
    const int* __restrict__ tok, const float* __restrict__ embed,
    const float* __restrict__ norm_w,
    const float* __restrict__ encW, const float* __restrict__ encb,
    const float* __restrict__ decW, const float* __restrict__ decb,
    const float* __restrict__ Win, const float* __restrict__ WbX,
    const float* __restrict__ WaX, const float* __restrict__ WtX,
    const float* __restrict__ WbV, const float* __restrict__ WaV,
    const float* __restrict__ WtV,
    const float* __restrict__ b_beta, const float* __restrict__ b_alpha,
    const float* __restrict__ b_th,
    const float* __restrict__ Wgate, const float* __restrict__ Wskip,
    const float* __restrict__ Wout,
    const float* __restrict__ plif_w, const float* __restrict__ out_vth,
    float* __restrict__ out)
{
    const int blk  = blockIdx.x;           // 0..511
    const int tid  = threadIdx.x;
    const int warp = tid >> 5, lane = tid & 31;
    __shared__ float sh[4][16][4];

    // ---- init state (deterministic every replay) ----
    for (int i = blk * NTHR + tid; i < NBc * Bc * DNc; i += NBLK * NTHR) g_Vst[i] = 0.0f;
    for (int i = blk * NTHR + tid; i < NBc * Bc * Dc;  i += NBLK * NTHR) g_u[i]   = 0.0f;
    grid_sync();

    int par = 0;
    for (int t = 0; t < Sc; ++t) {
        // ================= encoder: 2 rows/block =================
        {
            int j0 = blk * 2;
            const float* e0 = embed + (size_t)__ldg(tok + 0 * Sc + t) * Dc;
            const float* e1 = embed + (size_t)__ldg(tok + 1 * Sc + t) * Dc;
            const float* e2 = embed + (size_t)__ldg(tok + 2 * Sc + t) * Dc;
            const float* e3 = embed + (size_t)__ldg(tok + 3 * Sc + t) * Dc;
            float acc[8];
#pragma unroll
            for (int i = 0; i < 8; ++i) acc[i] = 0.0f;
            passN<2, 2>(encW + (size_t)j0 * Dc, Dc, e0, e1, e2, e3, warp, lane, acc);
            reduceN<8>(acc, sh[0], warp, lane);
            __syncthreads();
            if (tid < 8) {
                int r = tid >> 2, b = tid & 3;
                int j = j0 + r;
                float s = sh[0][tid][0] + sh[0][tid][1] + sh[0][tid][2] + sh[0][tid][3];
                float res = sigmf_(s + encb[j]);
#pragma unroll
                for (int k = 0; k < Kc; ++k) {
                    float bit = (res >= 0.5f) ? 1.0f : 0.0f;
                    g_frames[((size_t)k * Bc + b) * Dc + j] = bit;
                    res = (res - 0.5f * bit) * 2.0f;
                }
                g_decoded[b * Dc + j] = 0.0f;
            }
        }
        grid_sync();

        // ================= K frames x NB blocks =================
        for (int k = 0; k < Kc; ++k) {
            int xin = k;                         // frame k feeds block 0
            for (int i = 0; i < NBc; ++i) {
                // ---- blk1: 4 rows/block, fused 7-GEMV + V update + spike ----
                {
                    size_t n0 = (size_t)blk * 4;
                    const float* x  = xsel_ptr(xin);
                    const float* Vi = g_Vst + ((size_t)par * NBc + i) * Bc * DNc;
                    float*       Vo = g_Vst + ((size_t)(par ^ 1) * NBc + i) * Bc * DNc;
                    const float* x0 = x;            const float* x1 = x + Dc;
                    const float* x2 = x + 2 * Dc;   const float* x3 = x + 3 * Dc;
                    const float* v0 = Vi;           const float* v1 = Vi + DNc;
                    const float* v2 = Vi + 2 * DNc; const float* v3 = Vi + 3 * DNc;
                    size_t rX = ((size_t)i * DNc + n0) * Dc;
                    size_t rV = ((size_t)i * DNc + n0) * DNc;
                    float acc[16];
#pragma unroll
                    for (int q = 0; q < 16; ++q) acc[q] = 0.0f;
                    passN<4, 2>(WbX + rX, Dc,  x0, x1, x2, x3, warp, lane, acc);
                    passN<4, 4>(WbV + rV, DNc, v0, v1, v2, v3, warp, lane, acc);
                    reduceN<16>(acc, sh[0], warp, lane);
#pragma unroll
                    for (int q = 0; q < 16; ++q) acc[q] = 0.0f;
                    passN<4, 2>(WaX + rX, Dc,  x0, x1, x2, x3, warp, lane, acc);
                    passN<4, 4>(WaV + rV, DNc, v0, v1, v2, v3, warp, lane, acc);
                    reduceN<16>(acc, sh[1], warp, lane);
#pragma unroll
                    for (int q = 0; q < 16; ++q) acc[q] = 0.0f;
                    passN<4, 2>(WtX + rX, Dc,  x0, x1, x2, x3, warp, lane, acc);
                    passN<4, 4>(WtV + rV, DNc, v0, v1, v2, v3, warp, lane, acc);
                    reduceN<16>(acc, sh[2], warp, lane);
#pragma unroll
                    for (int q = 0; q < 16; ++q) acc[q] = 0.0f;
                    passN<4, 2>(Win + rX, Dc, x0, x1, x2, x3, warp, lane, acc);
                    reduceN<16>(acc, sh[3], warp, lane);
                    __syncthreads();
                    if (tid < 16) {
                        int r = tid >> 2, b = tid & 3;
                        size_t n = n0 + r;
                        float pB = sh[0][tid][0] + sh[0][tid][1] + sh[0][tid][2] + sh[0][tid][3];
                        float pA = sh[1][tid][0] + sh[1][tid][1] + sh[1][tid][2] + sh[1][tid][3];
                        float pT = sh[2][tid][0] + sh[2][tid][1] + sh[2][tid][2] + sh[2][tid][3];
                        float pI = sh[3][tid][0] + sh[3][tid][1] + sh[3][tid][2] + sh[3][tid][3];
                        float beta  = sigmf_(pB + b_beta[(size_t)i * DNc + n]);
                        float alpha = sigmf_(pA + b_alpha[(size_t)i * DNc + n]);
                        float vth   = 0.1f + softplusf_(pT + b_th[(size_t)i * DNc + n]);
                        float vold  = Vi[(size_t)b * DNc + n];
                        float vnew  = beta * vold + alpha * pI;
                        float spv   = ((vnew - vth) >= 0.0f) ? 1.0f : 0.0f;
                        Vo[(size_t)b * DNc + n]   = vnew - spv * vth;
                        g_sp[(size_t)b * DNc + n] = spv;
                    }
                }
                grid_sync();

                // ---- blk2: 2 rows/block, gate/skip/out + PLIF + output spike ----
                {
                    int xo = Kc + (i & 1);
                    size_t j0 = (size_t)blk * 2;
                    const float* x = xsel_ptr(xin);
                    float* xout = g_xbuf[xo - Kc];
                    const float* x0 = x;           const float* x1 = x + Dc;
                    const float* x2 = x + 2 * Dc;  const float* x3 = x + 3 * Dc;
                    const float* s0 = g_sp;            const float* s1 = g_sp + DNc;
                    const float* s2 = g_sp + 2 * DNc;  const float* s3 = g_sp + 3 * DNc;
                    size_t rD = ((size_t)i * Dc + j0) * Dc;
                    size_t rN = ((size_t)i * Dc + j0) * DNc;
                    float acc[8];
#pragma unroll
                    for (int q = 0; q < 8; ++q) acc[q] = 0.0f;
                    passN<2, 2>(Wgate + rD, Dc, x0, x1, x2, x3, warp, lane, acc);
                    reduceN<8>(acc, sh[0], warp, lane);
#pragma unroll
                    for (int q = 0; q < 8; ++q) acc[q] = 0.0f;
                    passN<2, 2>(Wskip + rD, Dc, x0, x1, x2, x3, warp, lane, acc);
                    reduceN<8>(acc, sh[1], warp, lane);
#pragma unroll
                    for (int q = 0; q < 8; ++q) acc[q] = 0.0f;
                    passN<2, 4>(Wout + rN, DNc, s0, s1, s2, s3, warp, lane, acc);
                    reduceN<8>(acc, sh[2], warp, lane);
                    __syncthreads();
                    if (tid < 8) {
                        int r = tid >> 2, b = tid & 3;
                        size_t j = j0 + r;
                        float g  = sh[0][tid][0] + sh[0][tid][1] + sh[0][tid][2] + sh[0][tid][3];
                        float sk = sh[1][tid][0] + sh[1][tid][1] + sh[1][tid][2] + sh[1][tid][3];
                        float o  = sh[2][tid][0] + sh[2][tid][1] + sh[2][tid][2] + sh[2][tid][3];
                        float cur = sigmf_(g) * o + sk;
                        float tau = sigmf_(plif_w[i]);
                        float vt  = out_vth[i];
                        size_t ui = ((size_t)i * Bc + b) * Dc + j;
                        float uu = g_u[ui];
                        uu = uu + (cur - uu) * tau;
                        float so = ((uu - vt) >= 0.0f) ? 1.0f : 0.0f;
                        g_u[ui] = (1.0f - so) * uu;
                        xout[(size_t)b * Dc + j] = so;
                        if (i == NBc - 1) {
                            float wk = 1.0f / (float)(1 << (k + 1));
                            g_decoded[(size_t)b * Dc + j] += wk * so;
                        }
                    }
                    xin = xo;
                }
                grid_sync();
            }
            par ^= 1;                            // V ping-pong flips once per frame
        }

        // ================= decoder: 2 rows/block =================
        {
            size_t j0 = (size_t)blk * 2;
            const float* d0 = g_decoded;           const float* d1 = g_decoded + Dc;
            const float* d2 = g_decoded + 2 * Dc;  const float* d3 = g_decoded + 3 * Dc;
            float acc[8];
#pragma unroll
            for (int q = 0; q < 8; ++q) acc[q] = 0.0f;
            passN<2, 2>(decW + j0 * Dc, Dc, d0, d1, d2, d3, warp, lane, acc);
            reduceN<8>(acc, sh[0], warp, lane);
            __syncthreads();
            if (tid < 8) {
                int r = tid >> 2, b = tid & 3;
                size_t j = j0 + r;
                float s = sh[0][tid][0] + sh[0][tid][1] + sh[0][tid][2] + sh[0][tid][3];
                g_hh[(size_t)b * Dc + j] = s + decb[j];
            }
        }
        grid_sync();

        // ================= RMSNorm (block 0 only) =================
        if (blk == 0) {
            __shared__ float srstd[Bc];
            if (warp < Bc) {
                float s = 0.0f;
                for (int j = lane; j < Dc; j += 32) {
                    float v = g_hh[warp * Dc + j];
                    s = fmaf(v, v, s);
                }
                s = warp_sum(s);
                if (lane == 0) srstd[warp] = 1.0f / sqrtf(s / (float)Dc + 1e-6f);
            }
            __syncthreads();
            for (int idx = tid; idx < Bc * Dc; idx += NTHR) {
                g_hh[idx] = g_hh[idx] * norm_w[idx & (Dc - 1)] * srstd[idx >> 10];
            }
        }
        grid_sync();

        // ================= LM head: 75 x (512 blocks x 4 rows) =================
        {
            const float* h0 = g_hh;           const float* h1 = g_hh + Dc;
            const float* h2 = g_hh + 2 * Dc;  const float* h3 = g_hh + 3 * Dc;
            for (int it = 0; it < (VOCABc + NBLK * 4 - 1) / (NBLK * 4); ++it) {
                size_t v0 = (size_t)it * (NBLK * 4) + (size_t)blk * 4;
                if (v0 < VOCABc) {
                    float acc[16];
#pragma unroll
                    for (int q = 0; q < 16; ++q) acc[q] = 0.0f;
                    passN<4, 2>(embed + v0 * Dc, Dc, h0, h1, h2, h3, warp, lane, acc);
                    reduceN<16>(acc, sh[0], warp, lane);
                    __syncthreads();
                    if (tid < 16) {
                        int r = tid >> 2, b = tid & 3;
                        float s = sh[0][tid][0] + sh[0][tid][1] + sh[0][tid][2] + sh[0][tid][3];
                        out[((size_t)b * Sc + t) * VOCABc + v0 + r] = s;
                    }
                    __syncthreads();   // protect sh reuse across iterations
                }
            }
        }
        // no grid_sync needed here: the sync after enc(t+1) orders lmhead(t)
        // against the first writer of g_hh (dec at t+1).
    }
}

// ---------------- host driver: ONE graph node ----------------
extern "C" void kernel_launch(void* const* d_in, const int* in_sizes, int n_in,
                              void* d_out, int out_size)
{
    (void)in_sizes; (void)n_in; (void)out_size;
    snn_mono_kernel<<<NBLK, NTHR>>>(
        (const int*)d_in[0],  (const float*)d_in[1],  (const float*)d_in[2],
        (const float*)d_in[3], (const float*)d_in[4], (const float*)d_in[5],
        (const float*)d_in[6], (const float*)d_in[7], (const float*)d_in[8],
        (const float*)d_in[9], (const float*)d_in[10], (const float*)d_in[11],
        (const float*)d_in[12], (const float*)d_in[13], (const float*)d_in[14],
        (const float*)d_in[15], (const float*)d_in[16], (const float*)d_in[17],
        (const float*)d_in[18], (const float*)d_in[19], (const float*)d_in[20],
        (const float*)d_in[21], (float*)d_out);
}